// round 10
// baseline (speedup 1.0000x reference)
#include <cuda_runtime.h>

// Unfold (im2col): x[16,96,56,56] f32, 3x3 window, pad 1
// out[(bc*9 + ki*3+kj)*3136 + h*56+w] = x_pad[bc][h+ki][w+kj]
//
// v10 = v2 (proven best, 30.72us) + forced load/store interleave.
// ptxas front-batches all row loads (MLP_p1 ~5-8); per the B300 spread
// model, oe*MLP_p1 >> 16 causes cross-CTA L1tex queue contention and wave
// tail stretch. The per-row memory barrier forces load-row -> store-row
// phasing (MLP_p1 ~2), which costs nothing here (loads are L2 hits; the
// kernel is store/DRAM bound) and trims the slowest-CTA tail.

#define B_ 16
#define C_ 96
#define H_ 56
#define W_ 56
#define HW_ (H_ * W_)        // 3136
#define HW4_ (HW_ / 4)       // 784
#define NTHREADS_ (B_ * C_ * HW4_)   // 1,204,224 = 4704 * 256 exactly

__global__ __launch_bounds__(256) void unfold_kernel(
    const float* __restrict__ x, float* __restrict__ out)
{
    int tid = blockIdx.x * 256 + threadIdx.x;   // grid is exact, no guard

    int p4 = tid % HW4_;
    int bc = tid / HW4_;
    int p  = p4 * 4;
    int h  = p / W_;
    int w  = p - h * W_;      // multiple of 4

    const float* base  = x   + (size_t)bc * HW_;
    float*       obase = out + (size_t)bc * 9 * HW_ + p;

    #pragma unroll
    for (int r = 0; r < 3; r++) {
        int sh = h + r - 1;
        float v0, v1, v2, v3, v4, v5;   // [w-1, w, w+1, w+2, w+3, w+4]
        if (sh >= 0 && sh < H_) {
            const float* rp = base + sh * W_;
            float4 m = *reinterpret_cast<const float4*>(rp + w);   // aligned LDG.128
            v1 = m.x; v2 = m.y; v3 = m.z; v4 = m.w;
            v0 = (w > 0)      ? __ldg(rp + w - 1) : 0.f;
            v5 = (w + 4 < W_) ? __ldg(rp + w + 4) : 0.f;
        } else {
            v0 = v1 = v2 = v3 = v4 = v5 = 0.f;
        }

        float* o = obase + (size_t)(r * 3) * HW_;
        __stcs(reinterpret_cast<float4*>(o),           make_float4(v0, v1, v2, v3));
        __stcs(reinterpret_cast<float4*>(o + HW_),     make_float4(v1, v2, v3, v4));
        __stcs(reinterpret_cast<float4*>(o + 2 * HW_), make_float4(v2, v3, v4, v5));

        // phase fence: stop ptxas hoisting the next row's loads above these
        // stores (keeps MLP_p1 low -> less cross-CTA L1tex queue contention)
        asm volatile("" ::: "memory");
    }
}

extern "C" void kernel_launch(void* const* d_in, const int* in_sizes, int n_in,
                              void* d_out, int out_size)
{
    const float* x = (const float*)d_in[0];
    float* out = (float*)d_out;
    unfold_kernel<<<NTHREADS_ / 256, 256>>>(x, out);
}